// round 9
// baseline (speedup 1.0000x reference)
#include <cuda_runtime.h>
#include <cuda_fp16.h>
#include <cstdint>

// ---------------------------------------------------------------------------
// LSTMRegressor (B=256,T=512,D=64,H=512) x2 + FC512/ReLU + FC8
// R8: mma.sync persistent kernel, 4 warps/CTA (halved LDSM-B redundancy),
//     2-CTA cluster TMA multicast, x-chunk pre-issue across the grid barrier.
//   CTA (mh, ngrp): rows [mh*128,+128), hidden units [ngrp*8,+8) both layers.
//   Warp w owns rows [w*32, w*32+32) x all N=32 (gates i|f|g|o = 4 n-tiles).
// ---------------------------------------------------------------------------
#define NB       128
#define THREADS  128
#define NSTAGE   3
#define STAGE_B  32768u
#define WTILE_B  4096
#define WS_OFF   1024
#define HS_OFF   (WS_OFF + 25 * WTILE_B)            // 103424 (1KB aligned)
#define SMEM_BYTES (HS_OFF + NSTAGE * (int)STAGE_B) // 201728

__device__ __align__(128) __half g_x16[512 * 2 * 8192];      // [t][mh] 16KB tiles
__device__ __align__(128) __half g_h0[2][2 * 4 * 2 * 8192];  // [par][mh][kc][kh]
__device__ __align__(128) __half g_h1[2][2 * 4 * 2 * 8192];
__device__ float g_hlast[256 * 512];
__device__ unsigned g_bar_count;
__device__ unsigned g_bar_gen;

// ---------------------------------------------------------------------------
__device__ __forceinline__ uint32_t smem_u32(const void* p) {
    uint32_t a;
    asm("{ .reg .u64 t; cvta.to.shared.u64 t, %1; cvt.u32.u64 %0, t; }"
        : "=r"(a) : "l"(p));
    return a;
}
__device__ __forceinline__ float sigf(float x) {
    return __fdividef(1.0f, 1.0f + __expf(-x));
}
__device__ __forceinline__ float tanhfast(float x) {
    return 1.0f - __fdividef(2.0f, __expf(2.0f * x) + 1.0f);
}
__device__ __forceinline__ uint32_t swz(uint32_t off) {
    return off ^ ((off >> 3) & 0x70u);
}
__device__ __forceinline__ void mbar_init(uint32_t a, unsigned c) {
    asm volatile("mbarrier.init.shared.b64 [%0], %1;" :: "r"(a), "r"(c) : "memory");
}
__device__ __forceinline__ void mbar_arrive(uint32_t a) {
    asm volatile("mbarrier.arrive.shared.b64 _, [%0];" :: "r"(a) : "memory");
}
__device__ __forceinline__ void mbar_arrive_remote(uint32_t a) {
    asm volatile("mbarrier.arrive.shared::cluster.b64 _, [%0];" :: "r"(a) : "memory");
}
__device__ __forceinline__ void mbar_wait(uint32_t a, unsigned par) {
    asm volatile(
        "{\n\t.reg .pred P;\n"
        "W%=:\n\tmbarrier.try_wait.parity.acquire.cta.shared::cta.b64 P, [%0], %1;\n"
        "\t@P bra E%=;\n\tbra W%=;\nE%=:\n\t}"
        :: "r"(a), "r"(par) : "memory");
}
__device__ __forceinline__ void stg32(void* p, uint32_t v) {
    asm volatile("st.global.cg.b32 [%0], %1;" :: "l"(p), "r"(v) : "memory");
}
__device__ __forceinline__ void stgf(float* p, float v) {
    asm volatile("st.global.cg.f32 [%0], %1;" :: "l"(p), "f"(v) : "memory");
}
__device__ __forceinline__ void ldm4(uint32_t r[4], uint32_t addr) {
    asm volatile("ldmatrix.sync.aligned.m8n8.x4.shared.b16 {%0,%1,%2,%3}, [%4];"
                 : "=r"(r[0]), "=r"(r[1]), "=r"(r[2]), "=r"(r[3]) : "r"(addr));
}
__device__ __forceinline__ void mma16816(float d[4], const uint32_t a[4],
                                         const uint32_t b[2]) {
    asm volatile(
        "mma.sync.aligned.m16n8k16.row.col.f32.f16.f16.f32 "
        "{%0,%1,%2,%3}, {%4,%5,%6,%7}, {%8,%9}, {%0,%1,%2,%3};"
        : "+f"(d[0]), "+f"(d[1]), "+f"(d[2]), "+f"(d[3])
        : "r"(a[0]), "r"(a[1]), "r"(a[2]), "r"(a[3]), "r"(b[0]), "r"(b[1]));
}
__device__ __forceinline__ void grid_barrier() {
    __threadfence();
    __syncthreads();
    if (threadIdx.x == 0) {
        unsigned gen = *((volatile unsigned*)&g_bar_gen);
        unsigned arrived = atomicAdd(&g_bar_count, 1u);
        if (arrived == NB - 1) {
            g_bar_count = 0;
            __threadfence();
            atomicAdd(&g_bar_gen, 1u);
        } else {
            while (*((volatile unsigned*)&g_bar_gen) == gen) { __nanosleep(64); }
            __threadfence();
        }
    }
    __syncthreads();
}

// Producer: both CTAs expect_tx on local FULL; issuer (gid parity) multicasts.
__device__ __forceinline__ void issue_one(uint32_t FULL, uint32_t EMPTY,
                                          uint32_t HSB, unsigned gid,
                                          const void* src, uint32_t bytes,
                                          int rank) {
    const uint32_t st = gid % 3u;
    const unsigned ph = (gid / 3u) & 1u;
    mbar_wait(EMPTY + st * 8, ph ^ 1u);
    asm volatile("mbarrier.arrive.expect_tx.shared.b64 _, [%0], %1;"
                 :: "r"(FULL + st * 8), "r"(bytes) : "memory");
    if ((int)(gid & 1u) == rank)
        asm volatile(
            "cp.async.bulk.shared::cluster.global.mbarrier::complete_tx::bytes"
            ".multicast::cluster [%0], [%1], %2, [%3], %4;"
            :: "r"(HSB + st * STAGE_B), "l"(src), "r"(bytes),
               "r"(FULL + st * 8), "h"((unsigned short)0x3)
            : "memory");
}

// One staged chunk (nkh k-halves of 64): acc{0,1}[mt][nt] += A(32 rows) * W^T.
__device__ __forceinline__ void gemm_chunk(
    float a0[2][4][4], float a1[2][4][4],
    uint32_t sa, uint32_t w0k, uint32_t w1k,
    bool d0, bool d1, int nkh, int wid, int lane)
{
    const int rn = lane & 7;
    const uint32_t arow0 = (uint32_t)(wid * 32 + ((lane >> 3) & 1) * 8 + rn) * 128
                         + (uint32_t)((lane >> 4) * 8) * 2;
    const uint32_t brow0 = (uint32_t)((lane >> 4) * 8 + rn) * 128
                         + (uint32_t)(((lane >> 3) & 1) * 8) * 2;
    const uint32_t brow2 = brow0 + 2 * 8 * 128;
    for (int kh = 0; kh < nkh; ++kh) {
        const uint32_t saKH = sa + kh * 16384;
        const uint32_t w0t = w0k + kh * WTILE_B;
        const uint32_t w1t = w1k + kh * WTILE_B;
        #pragma unroll
        for (int ks = 0; ks < 4; ++ks) {
            uint32_t a[2][4];
            ldm4(a[0], saKH + swz(arow0 + ks * 32));
            ldm4(a[1], saKH + swz(arow0 + 16 * 128 + ks * 32));
            if (d0) {
                uint32_t b[4], c[4];
                ldm4(b, w0t + swz(brow0 + ks * 32));
                ldm4(c, w0t + swz(brow2 + ks * 32));
                #pragma unroll
                for (int mt = 0; mt < 2; ++mt) {
                    mma16816(a0[mt][0], a[mt], b + 0);
                    mma16816(a0[mt][1], a[mt], b + 2);
                    mma16816(a0[mt][2], a[mt], c + 0);
                    mma16816(a0[mt][3], a[mt], c + 2);
                }
            }
            if (d1) {
                uint32_t b[4], c[4];
                ldm4(b, w1t + swz(brow0 + ks * 32));
                ldm4(c, w1t + swz(brow2 + ks * 32));
                #pragma unroll
                for (int mt = 0; mt < 2; ++mt) {
                    mma16816(a1[mt][0], a[mt], b + 0);
                    mma16816(a1[mt][1], a[mt], b + 2);
                    mma16816(a1[mt][2], a[mt], c + 0);
                    mma16816(a1[mt][3], a[mt], c + 2);
                }
            }
        }
    }
}

// Shuffle-free cell update: nt 0..3 = i,f,g,o for the same (row, unit) pairs.
__device__ __forceinline__ void cell_update(
    float acc[2][4][4], float cst[2][2][2], char* gdst, float* hlast,
    int ngrp, int mh, int wid, int lane)
{
    const int q   = lane & 3;
    const int hid = ngrp * 8 + 2 * q;
    const int kc  = hid >> 7, kh = (hid >> 6) & 1, kel = hid & 63;
    char* tile = gdst + ((size_t)((mh * 4 + kc) * 2 + kh)) * 16384;
    #pragma unroll
    for (int mt = 0; mt < 2; ++mt) {
        #pragma unroll
        for (int rh = 0; rh < 2; ++rh) {
            float hv[2];
            #pragma unroll
            for (int e = 0; e < 2; ++e) {
                const int d = rh * 2 + e;
                float ig = sigf(acc[mt][0][d]);
                float fg = sigf(acc[mt][1][d]);
                float gg = tanhfast(acc[mt][2][d]);
                float og = sigf(acc[mt][3][d]);
                float cc = fmaf(fg, cst[mt][rh][e], ig * gg);
                cst[mt][rh][e] = cc;
                hv[e] = og * tanhfast(cc);
            }
            const int row = wid * 32 + mt * 16 + (lane >> 2) + rh * 8;
            __half2 h2 = __floats2half2_rn(hv[0], hv[1]);
            stg32(tile + swz((uint32_t)row * 128 + kel * 2), *(uint32_t*)&h2);
            if (hlast) {
                const int b = mh * 128 + row;
                stgf(hlast + (size_t)b * 512 + hid,     hv[0]);
                stgf(hlast + (size_t)b * 512 + hid + 1, hv[1]);
            }
        }
    }
}

// ---------------------------------------------------------------------------
__global__ void __launch_bounds__(THREADS, 1) __cluster_dims__(2, 1, 1)
lstm_mma_kernel(
    const float* __restrict__ x,
    const float* __restrict__ Wih0, const float* __restrict__ Whh0,
    const float* __restrict__ bi0,  const float* __restrict__ bh0,
    const float* __restrict__ Wih1, const float* __restrict__ Whh1,
    const float* __restrict__ bi1,  const float* __restrict__ bh1,
    const float* __restrict__ Wfc1, const float* __restrict__ bfc1,
    const float* __restrict__ Wfc2, const float* __restrict__ bfc2,
    float* __restrict__ out)
{
    extern __shared__ char smem[];
    const uint32_t sbase = smem_u32(smem);
    const uint32_t FULL  = sbase;            // 3 x 8B
    const uint32_t EMPTY = sbase + 64;       // 3 x 8B
    const uint32_t WSB   = sbase + WS_OFF;
    const uint32_t HSB   = sbase + HS_OFF;

    const int tid  = threadIdx.x;
    const int lane = tid & 31;
    const int wid  = tid >> 5;
    const int c    = blockIdx.x;
    const int rank = c & 1;                  // cluster CTA rank
    const int mh   = (c >> 1) & 1;           // batch half (rows mh*128..)
    const int ngrp = ((c >> 2) << 1) | rank; // hidden-unit group (8 units)

    if (tid == 0) {
        #pragma unroll
        for (int s = 0; s < NSTAGE; ++s) {
            mbar_init(FULL + s * 8, 1);
            mbar_init(EMPTY + s * 8, 8);     // 4 warps x 2 CTAs
        }
    }
    __syncthreads();
    asm volatile("barrier.cluster.arrive.aligned;" ::: "memory");
    asm volatile("barrier.cluster.wait.aligned;" ::: "memory");

    uint32_t rEMPTY;
    asm("mapa.shared::cluster.u32 %0, %1, %2;"
        : "=r"(rEMPTY) : "r"(EMPTY), "r"(rank ^ 1));

    // ---- weights -> 25 resident fp16 SW128 tiles [32 gate cols x 64 k] ----
    for (int idx = tid; idx < 800; idx += THREADS) {
        const int ch = idx >> 5, rowi = idx & 31;
        const float* Wsrc; int ld, k0;
        if (ch == 0)      { Wsrc = Wih0; ld = 64;  k0 = 0; }
        else if (ch < 9)  { Wsrc = Whh0; ld = 512; k0 = (ch - 1) * 64; }
        else if (ch < 17) { Wsrc = Wih1; ld = 512; k0 = (ch - 9) * 64; }
        else              { Wsrc = Whh1; ld = 512; k0 = (ch - 17) * 64; }
        const int g = rowi >> 3, j = rowi & 7;
        const float* src = Wsrc + (size_t)(g * 512 + ngrp * 8 + j) * ld + k0;
        char* tb = smem + WS_OFF + ch * WTILE_B;
        for (int k = 0; k < 64; k += 2)
            *(__half2*)(tb + swz((uint32_t)rowi * 128 + k * 2)) =
                __floats2half2_rn(src[k], src[k + 1]);
    }

    // ---- biases: nt = gate, cols = units 2q,2q+1 ----
    const int q = lane & 3;
    float bias0[4][2], bias1[4][2];
    #pragma unroll
    for (int nt = 0; nt < 4; ++nt)
        #pragma unroll
        for (int e = 0; e < 2; ++e) {
            const int gc = nt * 512 + ngrp * 8 + 2 * q + e;
            bias0[nt][e] = bi0[gc] + bh0[gc];
            bias1[nt][e] = bi1[gc] + bh1[gc];
        }

    // ---- x -> fp16 swizzled 16KB tiles [t][mh2]; 8 tiles per CTA ----
    for (int w = 0; w < 8; ++w) {
        const int ti = c * 8 + w;
        const int t = ti >> 1, mh2 = ti & 1;
        char* dst = (char*)g_x16 + (size_t)ti * 16384;
        for (int p = 0; p < 32; ++p) {
            const int elem = tid + p * THREADS;       // 0..4095
            const int row = elem >> 5, kp = elem & 31;
            const float2 v = *(const float2*)(
                x + ((size_t)(mh2 * 128 + row) * 512 + t) * 64 + kp * 2);
            *(__half2*)(dst + swz((uint32_t)row * 128 + kp * 4)) =
                __floats2half2_rn(v.x, v.y);
        }
    }
    asm volatile("fence.proxy.async.global;" ::: "memory");
    grid_barrier();

    float cst0[2][2][2] = {}, cst1[2][2][2] = {};
    unsigned cons = 0;
    uint32_t st_ = 0, sa_ = 0;
    bool pre = false;                // next tick's x chunk already issued?

    for (int t = 0; t <= 512; ++t) {
        const bool doL0  = (t < 512);
        const bool rec0  = doL0 && (t > 0);
        const bool doL1  = (t >= 1);
        const bool rec1  = (t >= 2);
        const bool h0grp = rec0 || doL1;

        // chunk list (in consumption order)
        const char* srcs[9];
        int nch = 0;
        if (doL0) srcs[nch++] = (const char*)g_x16 + ((size_t)t * 2 + mh) * 16384;
        if (h0grp) {
            const char* b = (const char*)g_h0[(t - 1) & 1] + (size_t)mh * 131072;
            for (int kc = 0; kc < 4; ++kc) srcs[nch++] = b + (size_t)kc * 32768;
        }
        if (rec1) {
            const char* b = (const char*)g_h1[t & 1] + (size_t)mh * 131072;
            for (int kc = 0; kc < 4; ++kc) srcs[nch++] = b + (size_t)kc * 32768;
        }

        const unsigned gc0 = cons;
        int pi = nch < NSTAGE ? nch : NSTAGE;
        if (tid == 0)
            for (int i2 = pre ? 1 : 0; i2 < pi; ++i2)
                issue_one(FULL, EMPTY, HSB, gc0 + i2, srcs[i2],
                          (doL0 && i2 == 0) ? 16384u : 32768u, rank);
        pre = false;

        float acc0[2][4][4], acc1[2][4][4];
        #pragma unroll
        for (int mt = 0; mt < 2; ++mt)
            #pragma unroll
            for (int nt = 0; nt < 4; ++nt) {
                acc0[mt][nt][0] = bias0[nt][0]; acc0[mt][nt][1] = bias0[nt][1];
                acc0[mt][nt][2] = bias0[nt][0]; acc0[mt][nt][3] = bias0[nt][1];
                acc1[mt][nt][0] = bias1[nt][0]; acc1[mt][nt][1] = bias1[nt][1];
                acc1[mt][nt][2] = bias1[nt][0]; acc1[mt][nt][3] = bias1[nt][1];
            }

        #define CPRE()                                                   \
            do { st_ = cons % 3u;                                        \
                 mbar_wait(FULL + st_ * 8, (cons / 3u) & 1u);            \
                 sa_ = HSB + st_ * STAGE_B; } while (0)
        #define CPOST()                                                  \
            do { if (lane == 0) {                                        \
                     mbar_arrive(EMPTY + st_ * 8);                       \
                     mbar_arrive_remote(rEMPTY + st_ * 8); }             \
                 ++cons;                                                 \
                 if (pi < nch) {                                         \
                     if (tid == 0)                                       \
                         issue_one(FULL, EMPTY, HSB, gc0 + pi,           \
                                   srcs[pi], 32768u, rank);              \
                     ++pi; } } while (0)

        if (doL0) {
            CPRE();
            gemm_chunk(acc0, acc1, sa_, WSB, WSB, true, false, 1, wid, lane);
            CPOST();
        }
        if (h0grp) {
            for (int kc = 0; kc < 4; ++kc) {
                CPRE();
                gemm_chunk(acc0, acc1, sa_,
                           WSB + (1 + kc * 2) * WTILE_B,
                           WSB + (9 + kc * 2) * WTILE_B,
                           rec0, doL1, 2, wid, lane);
                CPOST();
            }
        }
        if (doL0)
            cell_update(acc0, cst0, (char*)g_h0[t & 1], nullptr,
                        ngrp, mh, wid, lane);
        if (rec1) {
            for (int kc = 0; kc < 4; ++kc) {
                CPRE();
                gemm_chunk(acc1, acc0, sa_,
                           WSB + (17 + kc * 2) * WTILE_B, WSB,
                           true, false, 2, wid, lane);
                CPOST();
            }
        }

        // Pre-issue next tick's x chunk (static data) to hide TMA latency
        // behind the epilogue + grid barrier.
        if (t < 511) {
            if (tid == 0)
                issue_one(FULL, EMPTY, HSB, cons,
                          (const char*)g_x16 + ((size_t)(t + 1) * 2 + mh) * 16384,
                          16384u, rank);
            pre = true;
        }

        if (doL1)
            cell_update(acc1, cst1, (char*)g_h1[(t - 1) & 1],
                        (t == 512) ? g_hlast : nullptr, ngrp, mh, wid, lane);

        asm volatile("fence.proxy.async.global;" ::: "memory");
        grid_barrier();
    }

    // ---------------- FC head: batch rows [2*c, 2*c+2) ----------------
    float* sm  = (float*)smem;
    float* shA = sm;
    float* shZ = sm + 1024;
    const int r0 = 2 * c;
    for (int i = tid; i < 1024; i += THREADS) {
        int row = i >> 9, k = i & 511;
        shA[i] = __ldcg(g_hlast + (size_t)(r0 + row) * 512 + k);
    }
    __syncthreads();

    #pragma unroll
    for (int ii = 0; ii < 4; ++ii) {
        int cc = tid + THREADS * ii;
        float a0v = bfc1[cc];
        float a1v = a0v;
        const float4* wr  = (const float4*)(Wfc1 + (size_t)cc * 512);
        const float4* hv0 = (const float4*)shA;
        const float4* hv1 = (const float4*)(shA + 512);
        #pragma unroll 4
        for (int k4 = 0; k4 < 128; ++k4) {
            float4 w = wr[k4];
            float4 p = hv0[k4];
            float4 qv = hv1[k4];
            a0v = fmaf(w.x, p.x, a0v);  a0v = fmaf(w.y, p.y, a0v);
            a0v = fmaf(w.z, p.z, a0v);  a0v = fmaf(w.w, p.w, a0v);
            a1v = fmaf(w.x, qv.x, a1v); a1v = fmaf(w.y, qv.y, a1v);
            a1v = fmaf(w.z, qv.z, a1v); a1v = fmaf(w.w, qv.w, a1v);
        }
        shZ[cc]       = fmaxf(a0v, 0.f);
        shZ[512 + cc] = fmaxf(a1v, 0.f);
    }
    __syncthreads();

    #pragma unroll
    for (int oc2 = 0; oc2 < 2; ++oc2) {
        const int oc = wid * 2 + oc2;
        #pragma unroll
        for (int row = 0; row < 2; ++row) {
            const float4* zz = (const float4*)(shZ + row * 512);
            const float4* wf = (const float4*)(Wfc2 + (size_t)oc * 512);
            float s = 0.f;
            #pragma unroll
            for (int k4 = lane; k4 < 128; k4 += 32) {
                float4 ww = wf[k4];
                float4 zv = zz[k4];
                s = fmaf(ww.x, zv.x, s); s = fmaf(ww.y, zv.y, s);
                s = fmaf(ww.z, zv.z, s); s = fmaf(ww.w, zv.w, s);
            }
            #pragma unroll
            for (int off = 16; off; off >>= 1)
                s += __shfl_xor_sync(0xFFFFFFFFu, s, off);
            if (lane == 0) out[(r0 + row) * 8 + oc] = s + bfc2[oc];
        }
    }

    asm volatile("barrier.cluster.arrive.aligned;" ::: "memory");
    asm volatile("barrier.cluster.wait.aligned;" ::: "memory");
}

// ---------------------------------------------------------------------------
extern "C" void kernel_launch(void* const* d_in, const int* in_sizes, int n_in,
                              void* d_out, int out_size)
{
    const float* x    = (const float*)d_in[0];
    const float* Wih0 = (const float*)d_in[1];
    const float* Whh0 = (const float*)d_in[2];
    const float* bi0  = (const float*)d_in[3];
    const float* bh0  = (const float*)d_in[4];
    const float* Wih1 = (const float*)d_in[5];
    const float* Whh1 = (const float*)d_in[6];
    const float* bi1  = (const float*)d_in[7];
    const float* bh1  = (const float*)d_in[8];
    const float* Wfc1 = (const float*)d_in[9];
    const float* bfc1 = (const float*)d_in[10];
    const float* Wfc2 = (const float*)d_in[11];
    const float* bfc2 = (const float*)d_in[12];
    float* out = (float*)d_out;

    cudaFuncSetAttribute(lstm_mma_kernel,
                         cudaFuncAttributeMaxDynamicSharedMemorySize, SMEM_BYTES);
    lstm_mma_kernel<<<NB, THREADS, SMEM_BYTES>>>(
        x, Wih0, Whh0, bi0, bh0, Wih1, Whh1, bi1, bh1,
        Wfc1, bfc1, Wfc2, bfc2, out);
}

// round 13
// speedup vs baseline: 1.1000x; 1.1000x over previous
#include <cuda_runtime.h>
#include <cuda_fp16.h>
#include <cstdint>

// ---------------------------------------------------------------------------
// LSTMRegressor (B=256,T=512,D=64,H=512) x2 + FC512/ReLU + FC8
// R9: mma.sync persistent kernel, 8 warps split as 2 k-groups x 4 m-slabs.
//   Group g (warps 4g..4g+3) consumes chunks with local index parity g.
//   Warp slab s covers rows [s*32, s*32+32) x all N=32 (i|f|g|o n-tiles).
//   Partial accs merged via 16KB SMEM reduction at tick end.
//   2-CTA cluster TMA multicast; two producer threads (tid 0 / tid 128).
// ---------------------------------------------------------------------------
#define NB       128
#define THREADS  256
#define NSTAGE   3
#define STAGE_B  32768u
#define WTILE_B  4096
#define WS_OFF   1024
#define HS_OFF   (WS_OFF + 25 * WTILE_B)            // 103424
#define RED_OFF  (HS_OFF + NSTAGE * (int)STAGE_B)   // 201728
#define SMEM_BYTES (RED_OFF + 16384)                // 218112

__device__ __align__(128) __half g_x16[512 * 2 * 8192];      // [t][mh] 16KB tiles
__device__ __align__(128) __half g_h0[2][2 * 4 * 2 * 8192];  // [par][mh][kc][kh]
__device__ __align__(128) __half g_h1[2][2 * 4 * 2 * 8192];
__device__ float g_hlast[256 * 512];
__device__ unsigned g_bar_count;
__device__ unsigned g_bar_gen;

// ---------------------------------------------------------------------------
__device__ __forceinline__ uint32_t smem_u32(const void* p) {
    uint32_t a;
    asm("{ .reg .u64 t; cvta.to.shared.u64 t, %1; cvt.u32.u64 %0, t; }"
        : "=r"(a) : "l"(p));
    return a;
}
__device__ __forceinline__ float sigf(float x) {
    return __fdividef(1.0f, 1.0f + __expf(-x));
}
__device__ __forceinline__ float tanhfast(float x) {
    return 1.0f - __fdividef(2.0f, __expf(2.0f * x) + 1.0f);
}
__device__ __forceinline__ uint32_t swz(uint32_t off) {
    return off ^ ((off >> 3) & 0x70u);
}
__device__ __forceinline__ void mbar_init(uint32_t a, unsigned c) {
    asm volatile("mbarrier.init.shared.b64 [%0], %1;" :: "r"(a), "r"(c) : "memory");
}
__device__ __forceinline__ void mbar_arrive(uint32_t a) {
    asm volatile("mbarrier.arrive.shared.b64 _, [%0];" :: "r"(a) : "memory");
}
__device__ __forceinline__ void mbar_arrive_remote(uint32_t a) {
    asm volatile("mbarrier.arrive.shared::cluster.b64 _, [%0];" :: "r"(a) : "memory");
}
__device__ __forceinline__ void mbar_wait(uint32_t a, unsigned par) {
    asm volatile(
        "{\n\t.reg .pred P;\n"
        "W%=:\n\tmbarrier.try_wait.parity.acquire.cta.shared::cta.b64 P, [%0], %1;\n"
        "\t@P bra E%=;\n\tbra W%=;\nE%=:\n\t}"
        :: "r"(a), "r"(par) : "memory");
}
__device__ __forceinline__ void stg32(void* p, uint32_t v) {
    asm volatile("st.global.cg.b32 [%0], %1;" :: "l"(p), "r"(v) : "memory");
}
__device__ __forceinline__ void stgf(float* p, float v) {
    asm volatile("st.global.cg.f32 [%0], %1;" :: "l"(p), "f"(v) : "memory");
}
__device__ __forceinline__ void ldm4(uint32_t r[4], uint32_t addr) {
    asm volatile("ldmatrix.sync.aligned.m8n8.x4.shared.b16 {%0,%1,%2,%3}, [%4];"
                 : "=r"(r[0]), "=r"(r[1]), "=r"(r[2]), "=r"(r[3]) : "r"(addr));
}
__device__ __forceinline__ void mma16816(float d[4], const uint32_t a[4],
                                         const uint32_t b[2]) {
    asm volatile(
        "mma.sync.aligned.m16n8k16.row.col.f32.f16.f16.f32 "
        "{%0,%1,%2,%3}, {%4,%5,%6,%7}, {%8,%9}, {%0,%1,%2,%3};"
        : "+f"(d[0]), "+f"(d[1]), "+f"(d[2]), "+f"(d[3])
        : "r"(a[0]), "r"(a[1]), "r"(a[2]), "r"(a[3]), "r"(b[0]), "r"(b[1]));
}
__device__ __forceinline__ void grid_barrier() {
    __threadfence();
    __syncthreads();
    if (threadIdx.x == 0) {
        unsigned gen = *((volatile unsigned*)&g_bar_gen);
        unsigned arrived = atomicAdd(&g_bar_count, 1u);
        if (arrived == NB - 1) {
            g_bar_count = 0;
            __threadfence();
            atomicAdd(&g_bar_gen, 1u);
        } else {
            while (*((volatile unsigned*)&g_bar_gen) == gen) { __nanosleep(64); }
            __threadfence();
        }
    }
    __syncthreads();
}

// Producer: both CTAs expect_tx on local FULL; issuer (gid parity) multicasts.
__device__ __forceinline__ void issue_one(uint32_t FULL, uint32_t HSB,
                                          uint32_t EMPTY, unsigned gid,
                                          const void* src, uint32_t bytes,
                                          int rank) {
    const uint32_t st = gid % 3u;
    const unsigned ph = (gid / 3u) & 1u;
    mbar_wait(EMPTY + st * 8, ph ^ 1u);
    asm volatile("mbarrier.arrive.expect_tx.shared.b64 _, [%0], %1;"
                 :: "r"(FULL + st * 8), "r"(bytes) : "memory");
    if ((int)(gid & 1u) == rank)
        asm volatile(
            "cp.async.bulk.shared::cluster.global.mbarrier::complete_tx::bytes"
            ".multicast::cluster [%0], [%1], %2, [%3], %4;"
            :: "r"(HSB + st * STAGE_B), "l"(src), "r"(bytes),
               "r"(FULL + st * 8), "h"((unsigned short)0x3)
            : "memory");
}

// One staged chunk (nkh k-halves of 64): acc{0,1}[mt][nt] += A(32 rows) * W^T.
__device__ __forceinline__ void gemm_chunk(
    float a0[2][4][4], float a1[2][4][4],
    uint32_t sa, uint32_t w0t0, uint32_t w1t0,
    bool f0, bool f1, int nkh, int slab, int lane)
{
    const int rn = lane & 7;
    const uint32_t arow = (uint32_t)(slab * 32 + ((lane >> 3) & 1) * 8 + rn) * 128
                        + (uint32_t)((lane >> 4) * 8) * 2;
    const uint32_t brow0 = (uint32_t)((lane >> 4) * 8 + rn) * 128
                         + (uint32_t)(((lane >> 3) & 1) * 8) * 2;
    const uint32_t brow2 = brow0 + 2 * 8 * 128;
    for (int kh = 0; kh < nkh; ++kh) {
        const uint32_t saKH = sa + kh * 16384;
        const uint32_t w0t = w0t0 + kh * WTILE_B;
        const uint32_t w1t = w1t0 + kh * WTILE_B;
        #pragma unroll
        for (int ks = 0; ks < 4; ++ks) {
            uint32_t a[2][4];
            ldm4(a[0], saKH + swz(arow + ks * 32));
            ldm4(a[1], saKH + swz(arow + 16 * 128 + ks * 32));
            if (f0) {
                uint32_t b[4], cB[4];
                ldm4(b,  w0t + swz(brow0 + ks * 32));
                ldm4(cB, w0t + swz(brow2 + ks * 32));
                #pragma unroll
                for (int mt = 0; mt < 2; ++mt) {
                    mma16816(a0[mt][0], a[mt], b + 0);
                    mma16816(a0[mt][1], a[mt], b + 2);
                    mma16816(a0[mt][2], a[mt], cB + 0);
                    mma16816(a0[mt][3], a[mt], cB + 2);
                }
            }
            if (f1) {
                uint32_t b[4], cB[4];
                ldm4(b,  w1t + swz(brow0 + ks * 32));
                ldm4(cB, w1t + swz(brow2 + ks * 32));
                #pragma unroll
                for (int mt = 0; mt < 2; ++mt) {
                    mma16816(a1[mt][0], a[mt], b + 0);
                    mma16816(a1[mt][1], a[mt], b + 2);
                    mma16816(a1[mt][2], a[mt], cB + 0);
                    mma16816(a1[mt][3], a[mt], cB + 2);
                }
            }
        }
    }
}

// Shuffle-free cell update: nt 0..3 = i,f,g,o for the same (row, unit) pairs.
__device__ __forceinline__ void cell_update(
    float acc[2][4][4], float cst[2][2][2], char* gdst, float* hlast,
    int ngrp, int mh, int slab, int lane)
{
    const int q   = lane & 3;
    const int hid = ngrp * 8 + 2 * q;
    const int kc  = hid >> 7, kh = (hid >> 6) & 1, kel = hid & 63;
    char* tile = gdst + ((size_t)((mh * 4 + kc) * 2 + kh)) * 16384;
    #pragma unroll
    for (int mt = 0; mt < 2; ++mt) {
        #pragma unroll
        for (int rh = 0; rh < 2; ++rh) {
            float hv[2];
            #pragma unroll
            for (int e = 0; e < 2; ++e) {
                const int d = rh * 2 + e;
                float ig = sigf(acc[mt][0][d]);
                float fg = sigf(acc[mt][1][d]);
                float gg = tanhfast(acc[mt][2][d]);
                float og = sigf(acc[mt][3][d]);
                float cc = fmaf(fg, cst[mt][rh][e], ig * gg);
                cst[mt][rh][e] = cc;
                hv[e] = og * tanhfast(cc);
            }
            const int row = slab * 32 + mt * 16 + (lane >> 2) + rh * 8;
            __half2 h2 = __floats2half2_rn(hv[0], hv[1]);
            stg32(tile + swz((uint32_t)row * 128 + kel * 2), *(uint32_t*)&h2);
            if (hlast) {
                const int b = mh * 128 + row;
                stgf(hlast + (size_t)b * 512 + hid,     hv[0]);
                stgf(hlast + (size_t)b * 512 + hid + 1, hv[1]);
            }
        }
    }
}

// ---------------------------------------------------------------------------
__global__ void __launch_bounds__(THREADS, 1) __cluster_dims__(2, 1, 1)
lstm_mma_kernel(
    const float* __restrict__ x,
    const float* __restrict__ Wih0, const float* __restrict__ Whh0,
    const float* __restrict__ bi0,  const float* __restrict__ bh0,
    const float* __restrict__ Wih1, const float* __restrict__ Whh1,
    const float* __restrict__ bi1,  const float* __restrict__ bh1,
    const float* __restrict__ Wfc1, const float* __restrict__ bfc1,
    const float* __restrict__ Wfc2, const float* __restrict__ bfc2,
    float* __restrict__ out)
{
    extern __shared__ char smem[];
    const uint32_t sbase = smem_u32(smem);
    const uint32_t FULL  = sbase;            // 3 x 8B
    const uint32_t EMPTY = sbase + 64;       // 3 x 8B
    const uint32_t WSB   = sbase + WS_OFF;
    const uint32_t HSB   = sbase + HS_OFF;
    float* RED = (float*)(smem + RED_OFF);   // [4 slabs][32 regs][32 lanes]

    const int tid  = threadIdx.x;
    const int lane = tid & 31;
    const int wid  = tid >> 5;
    const int g    = wid >> 2;               // k-group 0/1
    const int slab = wid & 3;                // 32-row slab
    const bool isprod = (lane == 0 && slab == 0);   // tid 0 / tid 128
    const int c    = blockIdx.x;
    const int rank = c & 1;
    const int mh   = (c >> 1) & 1;
    const int ngrp = ((c >> 2) << 1) | rank;

    if (tid == 0) {
        #pragma unroll
        for (int s = 0; s < NSTAGE; ++s) {
            mbar_init(FULL + s * 8, 1);
            mbar_init(EMPTY + s * 8, 8);     // 4 consumer warps x 2 CTAs
        }
    }
    __syncthreads();
    asm volatile("barrier.cluster.arrive.aligned;" ::: "memory");
    asm volatile("barrier.cluster.wait.aligned;" ::: "memory");

    uint32_t rEMPTY;
    asm("mapa.shared::cluster.u32 %0, %1, %2;"
        : "=r"(rEMPTY) : "r"(EMPTY), "r"(rank ^ 1));

    // ---- weights -> 25 resident fp16 SW128 tiles [32 gate cols x 64 k] ----
    for (int idx = tid; idx < 800; idx += THREADS) {
        const int ch = idx >> 5, rowi = idx & 31;
        const float* Wsrc; int ld, k0;
        if (ch == 0)      { Wsrc = Wih0; ld = 64;  k0 = 0; }
        else if (ch < 9)  { Wsrc = Whh0; ld = 512; k0 = (ch - 1) * 64; }
        else if (ch < 17) { Wsrc = Wih1; ld = 512; k0 = (ch - 9) * 64; }
        else              { Wsrc = Whh1; ld = 512; k0 = (ch - 17) * 64; }
        const int gg2 = rowi >> 3, j = rowi & 7;
        const float* src = Wsrc + (size_t)(gg2 * 512 + ngrp * 8 + j) * ld + k0;
        char* tb = smem + WS_OFF + ch * WTILE_B;
        for (int k = 0; k < 64; k += 2)
            *(__half2*)(tb + swz((uint32_t)rowi * 128 + k * 2)) =
                __floats2half2_rn(src[k], src[k + 1]);
    }

    // ---- biases: nt = gate, cols = units 2q,2q+1 (applied by group 0 only) --
    const int q = lane & 3;
    float bias0[4][2], bias1[4][2];
    #pragma unroll
    for (int nt = 0; nt < 4; ++nt)
        #pragma unroll
        for (int e = 0; e < 2; ++e) {
            const int gc = nt * 512 + ngrp * 8 + 2 * q + e;
            bias0[nt][e] = bi0[gc] + bh0[gc];
            bias1[nt][e] = bi1[gc] + bh1[gc];
        }

    // ---- x -> fp16 swizzled 16KB tiles [t][mh2]; 8 tiles per CTA ----
    for (int w = 0; w < 8; ++w) {
        const int ti = c * 8 + w;
        const int t = ti >> 1, mh2 = ti & 1;
        char* dst = (char*)g_x16 + (size_t)ti * 16384;
        for (int p = 0; p < 16; ++p) {
            const int elem = tid + p * THREADS;       // 0..4095
            const int row = elem >> 5, kp = elem & 31;
            const float2 v = *(const float2*)(
                x + ((size_t)(mh2 * 128 + row) * 512 + t) * 64 + kp * 2);
            *(__half2*)(dst + swz((uint32_t)row * 128 + kp * 4)) =
                __floats2half2_rn(v.x, v.y);
        }
    }
    asm volatile("fence.proxy.async.global;" ::: "memory");
    grid_barrier();

    float cst0[2][2][2] = {}, cst1[2][2][2] = {};  // cst0: group0, cst1: group1
    unsigned cons = 0;
    bool pre = false;

    for (int t = 0; t <= 512; ++t) {
        const bool doL0  = (t < 512);
        const bool rec0  = doL0 && (t > 0);
        const bool doL1  = (t >= 1);
        const bool rec1  = (t >= 2);
        const bool h0grp = rec0 || doL1;

        // chunk descriptors (consumption order)
        const char* srcs[9];
        uint32_t szs[9];
        uint8_t w0i[9], w1i[9], f0a[9], f1a[9], nkha[9];
        int nch = 0;
        if (doL0) {
            srcs[nch] = (const char*)g_x16 + ((size_t)t * 2 + mh) * 16384;
            szs[nch] = 16384u; w0i[nch] = 0; w1i[nch] = 0;
            f0a[nch] = 1; f1a[nch] = 0; nkha[nch] = 1; ++nch;
        }
        if (h0grp) {
            const char* b = (const char*)g_h0[(t - 1) & 1] + (size_t)mh * 131072;
            for (int kc = 0; kc < 4; ++kc) {
                srcs[nch] = b + (size_t)kc * 32768; szs[nch] = 32768u;
                w0i[nch] = 1 + kc * 2; w1i[nch] = 9 + kc * 2;
                f0a[nch] = rec0; f1a[nch] = doL1; nkha[nch] = 2; ++nch;
            }
        }
        if (rec1) {
            const char* b = (const char*)g_h1[t & 1] + (size_t)mh * 131072;
            for (int kc = 0; kc < 4; ++kc) {
                srcs[nch] = b + (size_t)kc * 32768; szs[nch] = 32768u;
                w0i[nch] = 0; w1i[nch] = 17 + kc * 2;
                f0a[nch] = 0; f1a[nch] = 1; nkha[nch] = 2; ++nch;
            }
        }

        const unsigned gc0 = cons;
        const int limit = nch < NSTAGE ? nch : NSTAGE;

        // upfront issues (producer of each parity)
        if (isprod) {
            for (int i = (g == 0 && pre) ? 2 : g; i < limit; i += 2)
                issue_one(FULL, HSB, EMPTY, gc0 + i, srcs[i], szs[i], rank);
        }
        pre = false;
        int pig = limit + (((limit & 1) == g) ? 0 : 1);  // my next unissued

        float acc0[2][4][4], acc1[2][4][4];
        #pragma unroll
        for (int mt = 0; mt < 2; ++mt)
            #pragma unroll
            for (int nt = 0; nt < 4; ++nt)
                #pragma unroll
                for (int r = 0; r < 4; ++r) {
                    acc0[mt][nt][r] = (g == 0) ? bias0[nt][r & 1] : 0.f;
                    acc1[mt][nt][r] = (g == 0) ? bias1[nt][r & 1] : 0.f;
                }

        // consume my-parity chunks
        for (int i = g; i < nch; i += 2) {
            const unsigned gid = gc0 + i;
            const uint32_t st = gid % 3u;
            mbar_wait(FULL + st * 8, (gid / 3u) & 1u);
            gemm_chunk(acc0, acc1, HSB + st * STAGE_B,
                       WSB + w0i[i] * WTILE_B, WSB + w1i[i] * WTILE_B,
                       f0a[i] != 0, f1a[i] != 0, nkha[i], slab, lane);
            if (lane == 0) {
                mbar_arrive(EMPTY + st * 8);
                mbar_arrive_remote(rEMPTY + st * 8);
            }
            if (isprod && pig < nch) {
                issue_one(FULL, HSB, EMPTY, gc0 + pig, srcs[pig], szs[pig], rank);
                pig += 2;
            }
        }

        // pre-issue next tick's x chunk (static data only; t+1 <= 511)
        if (isprod && g == 0 && t < 511) {
            issue_one(FULL, HSB, EMPTY, gc0 + nch,
                      (const char*)g_x16 + ((size_t)(t + 1) * 2 + mh) * 16384,
                      16384u, rank);
            pre = true;
        }
        cons = gc0 + nch;

        // ---- reduction + cell updates ----
        __syncthreads();
        if (g == 1 && doL0) {                   // store acc0 partial
            float* Rp = RED + ((size_t)slab * 32) * 32 + lane;
            #pragma unroll
            for (int mt = 0; mt < 2; ++mt)
                #pragma unroll
                for (int nt = 0; nt < 4; ++nt)
                    #pragma unroll
                    for (int r = 0; r < 4; ++r)
                        Rp[(mt * 16 + nt * 4 + r) * 32] = acc0[mt][nt][r];
        }
        __syncthreads();
        if (g == 0) {
            if (doL0) {
                float* Rp = RED + ((size_t)slab * 32) * 32 + lane;
                #pragma unroll
                for (int mt = 0; mt < 2; ++mt)
                    #pragma unroll
                    for (int nt = 0; nt < 4; ++nt)
                        #pragma unroll
                        for (int r = 0; r < 4; ++r)
                            acc0[mt][nt][r] += Rp[(mt * 16 + nt * 4 + r) * 32];
                cell_update(acc0, cst0, (char*)g_h0[t & 1], nullptr,
                            ngrp, mh, slab, lane);
            }
            if (doL1) {                         // store acc1 partial (w/ bias)
                float* Rp = RED + ((size_t)slab * 32) * 32 + lane;
                #pragma unroll
                for (int mt = 0; mt < 2; ++mt)
                    #pragma unroll
                    for (int nt = 0; nt < 4; ++nt)
                        #pragma unroll
                        for (int r = 0; r < 4; ++r)
                            Rp[(mt * 16 + nt * 4 + r) * 32] = acc1[mt][nt][r];
            }
        }
        __syncthreads();
        if (g == 1 && doL1) {
            float* Rp = RED + ((size_t)slab * 32) * 32 + lane;
            #pragma unroll
            for (int mt = 0; mt < 2; ++mt)
                #pragma unroll
                for (int nt = 0; nt < 4; ++nt)
                    #pragma unroll
                    for (int r = 0; r < 4; ++r)
                        acc1[mt][nt][r] += Rp[(mt * 16 + nt * 4 + r) * 32];
            cell_update(acc1, cst1, (char*)g_h1[(t - 1) & 1],
                        (t == 512) ? g_hlast : nullptr, ngrp, mh, slab, lane);
        }

        asm volatile("fence.proxy.async.global;" ::: "memory");
        grid_barrier();
    }

    // ---------------- FC head: batch rows [2*c, 2*c+2) ----------------
    float* sm  = (float*)smem;
    float* shA = sm;
    float* shZ = sm + 1024;
    const int r0 = 2 * c;
    for (int i = tid; i < 1024; i += THREADS) {
        int row = i >> 9, k = i & 511;
        shA[i] = __ldcg(g_hlast + (size_t)(r0 + row) * 512 + k);
    }
    __syncthreads();

    #pragma unroll
    for (int ii = 0; ii < 2; ++ii) {
        int cc = tid + THREADS * ii;
        float a0v = bfc1[cc];
        float a1v = a0v;
        const float4* wr  = (const float4*)(Wfc1 + (size_t)cc * 512);
        const float4* hv0 = (const float4*)shA;
        const float4* hv1 = (const float4*)(shA + 512);
        #pragma unroll 4
        for (int k4 = 0; k4 < 128; ++k4) {
            float4 w = wr[k4];
            float4 p = hv0[k4];
            float4 qv = hv1[k4];
            a0v = fmaf(w.x, p.x, a0v);  a0v = fmaf(w.y, p.y, a0v);
            a0v = fmaf(w.z, p.z, a0v);  a0v = fmaf(w.w, p.w, a0v);
            a1v = fmaf(w.x, qv.x, a1v); a1v = fmaf(w.y, qv.y, a1v);
            a1v = fmaf(w.z, qv.z, a1v); a1v = fmaf(w.w, qv.w, a1v);
        }
        shZ[cc]       = fmaxf(a0v, 0.f);
        shZ[512 + cc] = fmaxf(a1v, 0.f);
    }
    __syncthreads();

    #pragma unroll
    for (int row = 0; row < 2; ++row) {
        const float4* zz = (const float4*)(shZ + row * 512);
        const float4* wf = (const float4*)(Wfc2 + (size_t)wid * 512);
        float s = 0.f;
        #pragma unroll
        for (int k4 = lane; k4 < 128; k4 += 32) {
            float4 ww = wf[k4];
            float4 zv = zz[k4];
            s = fmaf(ww.x, zv.x, s); s = fmaf(ww.y, zv.y, s);
            s = fmaf(ww.z, zv.z, s); s = fmaf(ww.w, zv.w, s);
        }
        #pragma unroll
        for (int off = 16; off; off >>= 1)
            s += __shfl_xor_sync(0xFFFFFFFFu, s, off);
        if (lane == 0) out[(r0 + row) * 8 + wid] = s + bfc2[wid];
    }

    asm volatile("barrier.cluster.arrive.aligned;" ::: "memory");
    asm volatile("barrier.cluster.wait.aligned;" ::: "memory");
}

// ---------------------------------------------------------------------------
extern "C" void kernel_launch(void* const* d_in, const int* in_sizes, int n_in,
                              void* d_out, int out_size)
{
    const float* x    = (const float*)d_in[0];
    const float* Wih0 = (const float*)d_in[1];
    const float* Whh0 = (const float*)d_in[2];
    const float* bi0  = (const float*)d_in[3];
    const float* bh0  = (const float*)d_in[4];
    const float* Wih1 = (const float*)d_in[5];
    const float* Whh1 = (const float*)d_in[6];
    const float* bi1  = (const float*)d_in[7];
    const float* bh1  = (const float*)d_in[8];
    const float* Wfc1 = (const float*)d_in[9];
    const float* bfc1 = (const float*)d_in[10];
    const float* Wfc2 = (const float*)d_in[11];
    const float* bfc2 = (const float*)d_in[12];
    float* out = (float*)d_out;

    cudaFuncSetAttribute(lstm_mma_kernel,
                         cudaFuncAttributeMaxDynamicSharedMemorySize, SMEM_BYTES);
    lstm_mma_kernel<<<NB, THREADS, SMEM_BYTES>>>(
        x, Wih0, Whh0, bi0, bh0, Wih1, Whh1, bi1, bh1,
        Wfc1, bfc1, Wfc2, bfc2, out);
}